// round 13
// baseline (speedup 1.0000x reference)
#include <cuda_runtime.h>
#include <cuda_bf16.h>
#include <math.h>
#include <stdint.h>

#define B_ 32
#define T_ 64
#define S_ 64
#define V_ 32000
#define E_ 512
#define U_ 1024
#define NBLK 148

// ---------------- scratch (static device globals; no allocs) ----------------
__device__ float g_emb  [B_*T_*E_];
__device__ float g_keys [B_*S_*U_];
__device__ float g_attn [B_*T_*U_];
__device__ float g_zpart[20*B_*4*U_];
__device__ float g_qpart[16*B_*U_];
__device__ float g_apart[16*B_*U_];
__device__ float g_aprev[B_*U_];
__device__ float g_h    [B_*U_];
__device__ float g_c    [B_*U_];
__device__ float g_ctx  [B_*U_];
__device__ unsigned int g_sync_ctr;
// bf16-split operands for tensor-core output GEMM
__device__ __nv_bfloat16 g_Ah[B_*T_*U_];
__device__ __nv_bfloat16 g_Al[B_*T_*U_];
__device__ __nv_bfloat16 g_Bh[V_*U_];
__device__ __nv_bfloat16 g_Bl[V_*U_];

__device__ __forceinline__ float tanh_fast(float x){
    float r; asm("tanh.approx.f32 %0, %1;" : "=f"(r) : "f"(x)); return r;
}
__device__ __forceinline__ float sigmoid_acc(float x){
    return 1.0f / (1.0f + expf(-x));
}

// ---- packed f32x2 helpers ----
__device__ __forceinline__ unsigned long long pack2(float a, float b){
    unsigned long long r;
    asm("mov.b64 %0, {%1, %2};" : "=l"(r) : "f"(a), "f"(b));
    return r;
}
__device__ __forceinline__ void unpack2(unsigned long long v, float& a, float& b){
    asm("mov.b64 {%0, %1}, %2;" : "=f"(a), "=f"(b) : "l"(v));
}
#define FMA2(acc, x, w) \
    asm("fma.rn.f32x2 %0, %1, %2, %0;" : "+l"(acc) : "l"(x), "l"(w))

// ---- sub-block (128-thread) named barrier ----
__device__ __forceinline__ void subbar(int sub){
    asm volatile("bar.sync %0, 128;" :: "r"(sub + 1) : "memory");
}

// ---- grid-wide barrier (monotonic counter; reset each launch) ----
__global__ void reset_sync(){ g_sync_ctr = 0u; }

__device__ __forceinline__ void gsync(unsigned int& expect){
    __syncthreads();
    if (threadIdx.x == 0){
        expect += NBLK;
        __threadfence();
        atomicAdd(&g_sync_ctr, 1u);
        unsigned int v;
        do {
            asm volatile("ld.acquire.gpu.u32 %0, [%1];" : "=r"(v) : "l"(&g_sync_ctr));
        } while (v < expect);
    }
    __syncthreads();
}

// ---------------- init h/c ----------------
__global__ void init_hc(const float* __restrict__ h0, const float* __restrict__ c0){
    int i = blockIdx.x * blockDim.x + threadIdx.x;
    if (i < B_*U_){ g_h[i] = h0[i]; g_c[i] = c0[i]; }
}

// ---------------- embedding gather ----------------
__global__ void embed_gather(const int* __restrict__ y, const float* __restrict__ emb){
    int bt = blockIdx.x;
    int b = bt / T_, t = bt % T_;
    int tok = (t == 0) ? 1 : y[b*T_ + t - 1];
    const float4* src = (const float4*)(emb + (long long)tok * E_);
    float4* dst = (float4*)(g_emb + (long long)bt * E_);
    int i = threadIdx.x;
    if (i < E_/4) dst[i] = src[i];
}

// ================= persistent recurrence kernel phases =====================

__device__ __forceinline__ void z_tile(float* xs, int stid, int sub,
        int jb, int kb, int t,
        const float* __restrict__ Wx, const float* __restrict__ Wh){
    int j = jb*128 + stid;
    const float* xp; long long xst; const float* wp;
    if (kb < 4){
        xp  = g_emb + (long long)t*E_ + kb*128;
        xst = (long long)T_*E_;
        wp  = Wx + (long long)(kb*128)*4096;
    } else if (kb < 12){
        xp  = g_aprev + (kb-4)*128;
        xst = U_;
        wp  = Wx + (long long)(512 + (kb-4)*128)*4096;
    } else {
        xp  = g_h + (kb-12)*128;
        xst = U_;
        wp  = Wh + (long long)((kb-12)*128)*4096;
    }

    subbar(sub);                       // xs free from previous use
    int b = stid >> 2, kq = stid & 3;
    #pragma unroll
    for (int i = 0; i < 8; i++){
        int k = kq*32 + i*4;
        float4 v = *(const float4*)(xp + b*xst + k);
        xs[(k+0)*36+b] = v.x; xs[(k+1)*36+b] = v.y;
        xs[(k+2)*36+b] = v.z; xs[(k+3)*36+b] = v.w;
    }
    subbar(sub);

    unsigned long long acc2[16];
    #pragma unroll
    for (int i = 0; i < 16; i++) acc2[i] = 0ull;

    const float* w = wp + j;
    #pragma unroll 4
    for (int k = 0; k < 128; k += 4){
        float w0 = w[(long long)(k+0)*4096];
        float w1 = w[(long long)(k+1)*4096];
        float w2 = w[(long long)(k+2)*4096];
        float w3 = w[(long long)(k+3)*4096];
        #pragma unroll
        for (int kk = 0; kk < 4; kk++){
            float wk = (kk==0)?w0:(kk==1)?w1:(kk==2)?w2:w3;
            unsigned long long wk2 = pack2(wk, wk);
            #pragma unroll
            for (int b4 = 0; b4 < 8; b4++){
                const float4 xv = *(const float4*)&xs[(k+kk)*36 + b4*4];
                unsigned long long x01 = pack2(xv.x, xv.y);
                unsigned long long x23 = pack2(xv.z, xv.w);
                FMA2(acc2[b4*2+0], x01, wk2);
                FMA2(acc2[b4*2+1], x23, wk2);
            }
        }
    }
    #pragma unroll
    for (int p = 0; p < 16; p++){
        float v0, v1; unpack2(acc2[p], v0, v1);
        g_zpart[((long long)kb*B_ + 2*p+0)*4096 + j] = v0;
        g_zpart[((long long)kb*B_ + 2*p+1)*4096 + j] = v1;
    }
}

__device__ __forceinline__ void lstm_elem(int idx, const float* __restrict__ bias){
    int b = idx >> 10, u = idx & 1023;
    float zi = bias[u], zj = bias[U_+u], zf = bias[2*U_+u], zo = bias[3*U_+u];
    #pragma unroll
    for (int p = 0; p < 20; p++){
        const float* zp = g_zpart + ((long long)p*B_ + b)*4096;
        zi += zp[u]; zj += zp[U_+u]; zf += zp[2*U_+u]; zo += zp[3*U_+u];
    }
    float c  = g_c[idx];
    float cn = sigmoid_acc(zf + 1.0f) * c + sigmoid_acc(zi) * tanhf(zj);
    g_c[idx] = cn;
    g_h[idx] = sigmoid_acc(zo) * tanhf(cn);
}

__device__ __forceinline__ void q_tile(float* xs, int stid, int sub,
        int jb, int kb, const float* __restrict__ Wq){
    int j  = jb*128 + stid;
    int r0 = kb * 64;

    subbar(sub);
    int b = stid >> 2, kq = stid & 3;
    #pragma unroll
    for (int i = 0; i < 4; i++){
        int k = kq*16 + i*4;
        float4 v = *(const float4*)(g_h + b*U_ + r0 + k);
        xs[(k+0)*36+b] = v.x; xs[(k+1)*36+b] = v.y;
        xs[(k+2)*36+b] = v.z; xs[(k+3)*36+b] = v.w;
    }
    subbar(sub);

    unsigned long long acc2[16];
    #pragma unroll
    for (int i = 0; i < 16; i++) acc2[i] = 0ull;

    const float* w = Wq + (long long)r0*U_ + j;
    #pragma unroll 4
    for (int k = 0; k < 64; k += 4){
        float w0 = w[(long long)(k+0)*U_];
        float w1 = w[(long long)(k+1)*U_];
        float w2 = w[(long long)(k+2)*U_];
        float w3 = w[(long long)(k+3)*U_];
        #pragma unroll
        for (int kk = 0; kk < 4; kk++){
            float wk = (kk==0)?w0:(kk==1)?w1:(kk==2)?w2:w3;
            unsigned long long wk2 = pack2(wk, wk);
            #pragma unroll
            for (int b4 = 0; b4 < 8; b4++){
                const float4 xv = *(const float4*)&xs[(k+kk)*36 + b4*4];
                unsigned long long x01 = pack2(xv.x, xv.y);
                unsigned long long x23 = pack2(xv.z, xv.w);
                FMA2(acc2[b4*2+0], x01, wk2);
                FMA2(acc2[b4*2+1], x23, wk2);
            }
        }
    }
    #pragma unroll
    for (int p = 0; p < 16; p++){
        float v0, v1; unpack2(acc2[p], v0, v1);
        g_qpart[((long long)kb*B_ + 2*p+0)*U_ + j] = v0;
        g_qpart[((long long)kb*B_ + 2*p+1)*U_ + j] = v1;
    }
}

__device__ __forceinline__ void attn_block(float* psm, int tid, int b,
        const float* __restrict__ enc, const float* __restrict__ v){
    float* q_s  = psm;          // 1024
    float* sc_s = psm + 1024;   // 64
    float* al_s = psm + 1088;   // 64

    for (int u = tid; u < U_; u += 512){
        float s = 0.0f;
        #pragma unroll
        for (int p = 0; p < 16; p++)
            s += g_qpart[((long long)p*B_ + b)*U_ + u];
        q_s[u] = s;
    }
    __syncthreads();

    int warp = tid >> 5, lane = tid & 31;
    #pragma unroll
    for (int si = 0; si < 4; si++){
        int s = warp*4 + si;
        const float* kp = g_keys + (long long)(b*S_ + s)*U_;
        float p = 0.f;
        for (int u = lane; u < U_; u += 32)
            p = fmaf(tanh_fast(kp[u] + q_s[u]), v[u], p);
        #pragma unroll
        for (int off = 16; off; off >>= 1)
            p += __shfl_xor_sync(0xffffffffu, p, off);
        if (lane == 0) sc_s[s] = p;
    }
    __syncthreads();

    if (warp == 0){
        float s0 = sc_s[lane], s1 = sc_s[lane+32];
        float m = fmaxf(s0, s1);
        #pragma unroll
        for (int off = 16; off; off >>= 1)
            m = fmaxf(m, __shfl_xor_sync(0xffffffffu, m, off));
        float e0 = expf(s0 - m), e1 = expf(s1 - m);
        float sum = e0 + e1;
        #pragma unroll
        for (int off = 16; off; off >>= 1)
            sum += __shfl_xor_sync(0xffffffffu, sum, off);
        float inv = 1.0f / sum;
        al_s[lane]    = e0 * inv;
        al_s[lane+32] = e1 * inv;
    }
    __syncthreads();

    for (int e = tid; e < U_; e += 512){
        const float* ep = enc + (long long)b*S_*U_ + e;
        float a = 0.f;
        #pragma unroll 16
        for (int s = 0; s < S_; s++)
            a = fmaf(al_s[s], ep[(long long)s*U_], a);
        g_ctx[(long long)b*U_ + e] = a;
    }
}

__device__ __forceinline__ void o_tile(float* xs, int stid, int sub,
        int jb, int kb, const float* __restrict__ Wa){
    int j = jb*128 + stid;
    const float* xp = (kb < 8) ? (g_h + kb*128) : (g_ctx + (kb-8)*128);
    const float* wp = Wa + (long long)(kb*128)*U_;

    subbar(sub);
    int b = stid >> 2, kq = stid & 3;
    #pragma unroll
    for (int i = 0; i < 8; i++){
        int k = kq*32 + i*4;
        float4 v = *(const float4*)(xp + b*U_ + k);
        xs[(k+0)*36+b] = v.x; xs[(k+1)*36+b] = v.y;
        xs[(k+2)*36+b] = v.z; xs[(k+3)*36+b] = v.w;
    }
    subbar(sub);

    unsigned long long acc2[16];
    #pragma unroll
    for (int i = 0; i < 16; i++) acc2[i] = 0ull;

    const float* w = wp + j;
    #pragma unroll 4
    for (int k = 0; k < 128; k += 4){
        float w0 = w[(long long)(k+0)*U_];
        float w1 = w[(long long)(k+1)*U_];
        float w2 = w[(long long)(k+2)*U_];
        float w3 = w[(long long)(k+3)*U_];
        #pragma unroll
        for (int kk = 0; kk < 4; kk++){
            float wk = (kk==0)?w0:(kk==1)?w1:(kk==2)?w2:w3;
            unsigned long long wk2 = pack2(wk, wk);
            #pragma unroll
            for (int b4 = 0; b4 < 8; b4++){
                const float4 xv = *(const float4*)&xs[(k+kk)*36 + b4*4];
                unsigned long long x01 = pack2(xv.x, xv.y);
                unsigned long long x23 = pack2(xv.z, xv.w);
                FMA2(acc2[b4*2+0], x01, wk2);
                FMA2(acc2[b4*2+1], x23, wk2);
            }
        }
    }
    #pragma unroll
    for (int p = 0; p < 16; p++){
        float v0, v1; unpack2(acc2[p], v0, v1);
        g_apart[((long long)kb*B_ + 2*p+0)*U_ + j] = v0;
        g_apart[((long long)kb*B_ + 2*p+1)*U_ + j] = v1;
    }
}

#define PS_SMEM (4*128*36*4)   // 73728 bytes: 4 sub-blocks x xs[128][36]

__global__ __launch_bounds__(512, 1)
void step_persist(const float* __restrict__ Wx, const float* __restrict__ Wh,
                  const float* __restrict__ bias, const float* __restrict__ Wq,
                  const float* __restrict__ enc, const float* __restrict__ v_att,
                  const float* __restrict__ Wa){
    extern __shared__ float psm[];
    const int tid  = threadIdx.x;
    const int blk  = blockIdx.x;
    const int sub  = tid >> 7;
    const int stid = tid & 127;
    float* xs = psm + sub * (128*36);
    unsigned int expect = 0;

    for (int t = 0; t < T_; t++){
        // ---- P: reduce attnout partials of t-1 into aprev/g_attn ----
        if (blk < 32){
            int b = blk;
            for (int u = tid; u < U_; u += 512){
                if (t == 0){
                    g_aprev[b*U_ + u] = 0.0f;
                } else {
                    float s = 0.0f;
                    #pragma unroll
                    for (int p = 0; p < 16; p++)
                        s += g_apart[(p*B_ + b)*U_ + u];
                    g_attn[((long long)b*T_ + (t-1))*U_ + u] = s;
                    g_aprev[b*U_ + u] = s;
                }
            }
        }
        gsync(expect);
        // ---- Z: 640 tiles over 592 sub-slots ----
        for (int tile = blk*4 + sub; tile < 640; tile += 4*NBLK){
            z_tile(xs, stid, sub, tile & 31, tile >> 5, t, Wx, Wh);
        }
        gsync(expect);
        // ---- L: lstm pointwise ----
        {
            int idx = blk*512 + tid;
            if (idx < B_*U_) lstm_elem(idx, bias);
        }
        gsync(expect);
        // ---- Q: 128 tiles ----
        {
            int tile = blk*4 + sub;
            if (tile < 128) q_tile(xs, stid, sub, tile & 7, tile >> 3, Wq);
        }
        gsync(expect);
        // ---- A: attention softmax/context, 32 blocks ----
        if (blk < 32) attn_block(psm, tid, blk, enc, v_att);
        gsync(expect);
        // ---- O: 128 tiles ----
        {
            int tile = blk*4 + sub;
            if (tile < 128) o_tile(xs, stid, sub, tile & 7, tile >> 3, Wa);
        }
        gsync(expect);
    }
    // final reduction: write g_attn[:, 63, :]
    if (blk < 32){
        int b = blk;
        for (int u = tid; u < U_; u += 512){
            float s = 0.0f;
            #pragma unroll
            for (int p = 0; p < 16; p++)
                s += g_apart[(p*B_ + b)*U_ + u];
            g_attn[((long long)b*T_ + 63)*U_ + u] = s;
        }
    }
}

// ---------------- fp32 SGEMM (keys only, f32x2) ----------------
__global__ __launch_bounds__(256)
void sgemm128(const float* __restrict__ A, const float* __restrict__ Bm,
              const float* __restrict__ bias, float* __restrict__ C,
              int M, int N, int K){
    __shared__ float As[16][132];
    __shared__ float Bs[16][132];
    int tid = threadIdx.x;
    int tx = tid & 15, ty = tid >> 4;
    int row0 = blockIdx.x * 128, col0 = blockIdx.y * 128;

    int m0 = tid >> 2, kq = tid & 3;
    int kr = tid >> 5, n4 = tid & 31;

    unsigned long long acc2[8][4];
    #pragma unroll
    for (int i = 0; i < 8; i++)
        #pragma unroll
        for (int j = 0; j < 4; j++) acc2[i][j] = 0ull;

    const float* Ap  = A  + (long long)(row0 + m0)*K + kq*4;
    const float* Ap2 = Ap + (long long)64*K;
    const float* Bp  = Bm + (long long)kr*N + col0 + n4*4;
    const float* Bp2 = Bp + (long long)8*N;

    float4 pa0 = *(const float4*)Ap;
    float4 pa1 = *(const float4*)Ap2;
    float4 pb0 = *(const float4*)Bp;
    float4 pb1 = *(const float4*)Bp2;

    int nk = K >> 4;
    for (int kt = 0; kt < nk; kt++){
        As[kq*4+0][m0]    = pa0.x; As[kq*4+1][m0]    = pa0.y;
        As[kq*4+2][m0]    = pa0.z; As[kq*4+3][m0]    = pa0.w;
        As[kq*4+0][m0+64] = pa1.x; As[kq*4+1][m0+64] = pa1.y;
        As[kq*4+2][m0+64] = pa1.z; As[kq*4+3][m0+64] = pa1.w;
        *(float4*)&Bs[kr][n4*4]   = pb0;
        *(float4*)&Bs[kr+8][n4*4] = pb1;
        __syncthreads();

        if (kt + 1 < nk){
            pa0 = *(const float4*)(Ap  + (kt+1)*16);
            pa1 = *(const float4*)(Ap2 + (kt+1)*16);
            pb0 = *(const float4*)(Bp  + (long long)(kt+1)*16*N);
            pb1 = *(const float4*)(Bp2 + (long long)(kt+1)*16*N);
        }

        #pragma unroll
        for (int k = 0; k < 16; k++){
            float a[8];
            *(float4*)&a[0]  = *(const float4*)&As[k][ty*8];
            *(float4*)&a[4]  = *(const float4*)&As[k][ty*8+4];
            float4 b0 = *(const float4*)&Bs[k][tx*8];
            float4 b1 = *(const float4*)&Bs[k][tx*8+4];
            unsigned long long bb2[4];
            bb2[0] = pack2(b0.x, b0.y); bb2[1] = pack2(b0.z, b0.w);
            bb2[2] = pack2(b1.x, b1.y); bb2[3] = pack2(b1.z, b1.w);
            #pragma unroll
            for (int i = 0; i < 8; i++){
                unsigned long long ai = pack2(a[i], a[i]);
                #pragma unroll
                for (int j = 0; j < 4; j++)
                    FMA2(acc2[i][j], bb2[j], ai);
            }
        }
        __syncthreads();
    }

    float bv[8];
    #pragma unroll
    for (int j = 0; j < 8; j++) bv[j] = bias ? bias[col0 + tx*8 + j] : 0.0f;

    #pragma unroll
    for (int i = 0; i < 8; i++){
        float* cp = C + (long long)(row0 + ty*8 + i)*N + col0 + tx*8;
        float o[8];
        #pragma unroll
        for (int j = 0; j < 4; j++) unpack2(acc2[i][j], o[2*j], o[2*j+1]);
        float4 o0, o1;
        o0.x = o[0]+bv[0]; o0.y = o[1]+bv[1]; o0.z = o[2]+bv[2]; o0.w = o[3]+bv[3];
        o1.x = o[4]+bv[4]; o1.y = o[5]+bv[5]; o1.z = o[6]+bv[6]; o1.w = o[7]+bv[7];
        *(float4*)cp       = o0;
        *(float4*)(cp + 4) = o1;
    }
}

// ---------------- bf16 split: attn -> Ah, Al ----------------
__global__ void split_attn(){
    int i = blockIdx.x * blockDim.x + threadIdx.x;
    if (i >= B_*T_*U_) return;
    float a = g_attn[i];
    __nv_bfloat16 h = __float2bfloat16(a);
    g_Ah[i] = h;
    g_Al[i] = __float2bfloat16(a - __bfloat162float(h));
}

// ---------------- bf16 split + transpose: Wout[K,V] -> Bh/Bl [V,K] ---------
__global__ __launch_bounds__(256)
void split_wout(const float* __restrict__ W){
    __shared__ float s[32][33];
    int n0 = blockIdx.x * 32, k0 = blockIdx.y * 32;
    int tx = threadIdx.x & 31, ty = threadIdx.x >> 5;   // 32 x 8
    #pragma unroll
    for (int i = 0; i < 32; i += 8)
        s[ty+i][tx] = W[(long long)(k0+ty+i)*V_ + n0 + tx];   // s[k][n]
    __syncthreads();
    #pragma unroll
    for (int i = 0; i < 32; i += 8){
        int n = ty + i;
        float a = s[tx][n];                         // k = tx
        __nv_bfloat16 h = __float2bfloat16(a);
        long long o = (long long)(n0+n)*U_ + k0 + tx;
        g_Bh[o] = h;
        g_Bl[o] = __float2bfloat16(a - __bfloat162float(h));
    }
}

// ================= tensor-core output GEMM via mma.sync + ldmatrix =========
#define LDT     40
#define TEN     (128*LDT)
#define TEN_B   (TEN*2)
#define STAGE   (4*TEN)
#define STAGE_B (STAGE*2)
#define GM_SMEM (2*STAGE_B)

#define MMA16816(c, a, b) \
    asm volatile("mma.sync.aligned.m16n8k16.row.col.f32.bf16.bf16.f32 " \
        "{%0,%1,%2,%3}, {%4,%5,%6,%7}, {%8,%9}, {%0,%1,%2,%3};" \
        : "+f"((c)[0]), "+f"((c)[1]), "+f"((c)[2]), "+f"((c)[3]) \
        : "r"((a)[0]), "r"((a)[1]), "r"((a)[2]), "r"((a)[3]), \
          "r"((b)[0]), "r"((b)[1]))

#define LDSM4(R0, R1, R2, R3, ADDR) \
    asm volatile("ldmatrix.sync.aligned.m8n8.x4.shared.b16 {%0,%1,%2,%3}, [%4];" \
        : "=r"(R0), "=r"(R1), "=r"(R2), "=r"(R3) : "r"(ADDR))

__global__ __launch_bounds__(256)
void gemm_mma(const float* __restrict__ bias, float* __restrict__ C){
    extern __shared__ __nv_bfloat16 sm[];
    const int tid  = threadIdx.x;
    const int lane = tid & 31, wid = tid >> 5;
    const int wm   = wid >> 2, wn = wid & 3;
    const int g    = lane >> 2, c2 = (lane & 3) * 2;
    const long long row0 = (long long)blockIdx.x * 128;
    const long long col0 = (long long)blockIdx.y * 128;

    const uint32_t smb = (uint32_t)__cvta_generic_to_shared(sm);

    const uint32_t a_elem = (uint32_t)(wm*64 + ((lane>>3)&1)*8 + (lane&7)) * LDT
                          + (uint32_t)((lane>>4)*8);
    uint32_t b_elem[2];
    #pragma unroll
    for (int p = 0; p < 2; p++)
        b_elem[p] = (uint32_t)(wn*32 + p*16 + (lane>>4)*8 + (lane&7)) * LDT
                  + (uint32_t)(((lane>>3)&1)*8);

    const int lr = tid >> 1;
    const int lc = (tid & 1) * 16;
    const __nv_bfloat16* srcs[4] = {
        g_Ah + (row0 + lr)*U_, g_Al + (row0 + lr)*U_,
        g_Bh + (col0 + lr)*U_, g_Bl + (col0 + lr)*U_ };

    float acc[4][4][4];
    #pragma unroll
    for (int mi = 0; mi < 4; mi++)
        #pragma unroll
        for (int ni = 0; ni < 4; ni++)
            #pragma unroll
            for (int q = 0; q < 4; q++) acc[mi][ni][q] = 0.0f;

    auto issue = [&](int kt, int buf){
        __nv_bfloat16* st = sm + buf*STAGE;
        #pragma unroll
        for (int tn = 0; tn < 4; tn++){
            uint32_t d = (uint32_t)__cvta_generic_to_shared(st + tn*TEN + lr*LDT + lc);
            const __nv_bfloat16* s = srcs[tn] + kt*32 + lc;
            asm volatile(
                "cp.async.cg.shared.global [%0], [%1], 16;\n\t"
                "cp.async.cg.shared.global [%2], [%3], 16;"
                :: "r"(d), "l"(s), "r"(d + 16), "l"(s + 8) : "memory");
        }
        asm volatile("cp.async.commit_group;" ::: "memory");
    };

    issue(0, 0);
    for (int kt = 0; kt < 32; kt++){
        int buf = kt & 1;
        if (kt + 1 < 32){
            issue(kt + 1, buf ^ 1);
            asm volatile("cp.async.wait_group 1;" ::: "memory");
        } else {
            asm volatile("cp.async.wait_group 0;" ::: "memory");
        }
        __syncthreads();

        const uint32_t stage_b = smb + buf*STAGE_B;

        #pragma unroll
        for (int ks = 0; ks < 32; ks += 16){
            uint32_t bh[4][2], bl[4][2];
            #pragma unroll
            for (int p = 0; p < 2; p++){
                uint32_t ab = stage_b + 2*TEN_B + (b_elem[p] + ks)*2;
                LDSM4(bh[2*p][0], bh[2*p][1], bh[2*p+1][0], bh[2*p+1][1], ab);
                uint32_t al_ = stage_b + 3*TEN_B + (b_elem[p] + ks)*2;
                LDSM4(bl[2*p][0], bl[2*p][1], bl[2*p+1][0], bl[2*p+1][1], al_);
            }
            #pragma unroll
            for (int mi = 0; mi < 4; mi++){
                uint32_t ah[4], al[4];
                uint32_t aa = stage_b + (a_elem + mi*16*LDT + ks)*2;
                LDSM4(ah[0], ah[1], ah[2], ah[3], aa);
                uint32_t ab = stage_b + TEN_B + (a_elem + mi*16*LDT + ks)*2;
                LDSM4(al[0], al[1], al[2], al[3], ab);
                #pragma unroll
                for (int ni = 0; ni < 4; ni++){
                    MMA16816(acc[mi][ni], ah, bh[ni]);
                    MMA16816(acc[mi][ni], al, bh[ni]);
                    MMA16816(acc[mi][ni], ah, bl[ni]);
                }
            }
        }
        __syncthreads();
    }

    #pragma unroll
    for (int mi = 0; mi < 4; mi++){
        long long r = row0 + wm*64 + mi*16 + g;
        #pragma unroll
        for (int ni = 0; ni < 4; ni++){
            long long cc = col0 + wn*32 + ni*8 + c2;
            float b0 = bias[cc], b1 = bias[cc + 1];
            float2 v0, v1;
            v0.x = acc[mi][ni][0] + b0; v0.y = acc[mi][ni][1] + b1;
            v1.x = acc[mi][ni][2] + b0; v1.y = acc[mi][ni][3] + b1;
            *(float2*)(C + r*V_ + cc)       = v0;
            *(float2*)(C + (r + 8)*V_ + cc) = v1;
        }
    }
}

// ---------------- launch -----------------------------------------------------
extern "C" void kernel_launch(void* const* d_in, const int* in_sizes, int n_in,
                              void* d_out, int out_size){
    const int*   y     = (const int*)  d_in[0];
    const float* h0    = (const float*)d_in[1];
    const float* c0    = (const float*)d_in[2];
    const float* enc   = (const float*)d_in[3];
    const float* emb   = (const float*)d_in[4];
    const float* Wx    = (const float*)d_in[5];
    const float* Wh    = (const float*)d_in[6];
    const float* bvec  = (const float*)d_in[7];
    const float* Wk    = (const float*)d_in[8];
    const float* Wq    = (const float*)d_in[9];
    const float* v_att = (const float*)d_in[10];
    const float* Wa    = (const float*)d_in[11];
    const float* Wout  = (const float*)d_in[12];
    const float* bout  = (const float*)d_in[13];
    float* out = (float*)d_out;

    void* p;
    cudaGetSymbolAddress(&p, g_keys); float* keys_p = (float*)p;

    cudaFuncSetAttribute(gemm_mma, cudaFuncAttributeMaxDynamicSharedMemorySize, GM_SMEM);
    cudaFuncSetAttribute(step_persist, cudaFuncAttributeMaxDynamicSharedMemorySize, PS_SMEM);

    init_hc<<<128, 256>>>(h0, c0);
    embed_gather<<<B_*T_, 128>>>(y, emb);
    reset_sync<<<1, 1>>>();

    // Wout bf16 split+transpose (independent of the loop)
    split_wout<<<dim3(V_/32, U_/32), 256>>>(Wout);

    // keys = enc @ Wk (must precede persistent kernel's attention phase)
    sgemm128<<<dim3((B_*S_)/128, U_/128), 256>>>(enc, Wk, nullptr, keys_p,
                                                 B_*S_, U_, U_);

    // all 64 recurrence steps in one persistent kernel
    step_persist<<<NBLK, 512, PS_SMEM>>>(Wx, Wh, bvec, Wq, enc, v_att, Wa);

    // bf16 split of attn activations, then tensor-core output GEMM
    split_attn<<<(B_*T_*U_ + 255)/256, 256>>>();
    gemm_mma<<<dim3((B_*T_)/128, V_/128), 256, GM_SMEM>>>(bout, out);
}